// round 11
// baseline (speedup 1.0000x reference)
#include <cuda_runtime.h>
#include <cstddef>

// Fixed shapes
#define T_STEPS 336
#define NT      256          // 8 warps, 2 per SMSP
#define NCTAS   128          // 8 batch elems per CTA

typedef unsigned long long u64;

// ---- shared memory layout (float offsets) ----
// Weight segment: per k-pair block of 512 floats, block index (kp*PQ + lp):
//   [0..255]   if-plane: j*4 + {Wi_k, Wi_k1, Wf_k, Wf_k1}
//   [256..511] go-plane: j*4 + {Wg_k, Wg_k1, Wo_k, Wo_k1}
// kp = K-half of pair, lp = local pair index, PQ = K/4 blocks per half.
#define OFF_W0X 0            // K=16, PQ=4  -> 4096 floats
#define OFF_W0H 4096         // K=64, PQ=16 -> 16384
#define OFF_W1X 20480        // 16384
#define OFF_W1H 36864        // 16384
#define OFF_B   53248        // 512: [layer*256 + gate*64 + j]
#define OFF_X   53760        // 2 bufs x (8 elems x 16)
#define OFF_H0  54016        // 2 bufs x (8 elems x 64)
#define OFF_H1  55040        // 2 bufs x 512
#define SMEM_FLOATS 56064
#define SMEM_BYTES (SMEM_FLOATS * 4)   // 224,256 B < 232,448 cap

// ---- packed helpers ----
__device__ __forceinline__ u64 fma2(u64 a, u64 b, u64 c) {
    u64 d;
    asm("fma.rn.f32x2 %0, %1, %2, %3;" : "=l"(d) : "l"(a), "l"(b), "l"(c));
    return d;
}
__device__ __forceinline__ ulonglong2 lds2(const float* p) {
    return *reinterpret_cast<const ulonglong2*>(p);
}
__device__ __forceinline__ float foldadd(u64 v) {
    float lo, hi;
    asm("mov.b64 {%0,%1}, %2;" : "=f"(lo), "=f"(hi) : "l"(v));
    return lo + hi;
}
__device__ __forceinline__ float sigf(float x) {
    return __fdividef(1.0f, 1.0f + __expf(-x));
}
__device__ __forceinline__ float tanhe(float x) {
    return 1.0f - __fdividef(2.0f, __expf(2.0f * x) + 1.0f);
}

// GEMM over NCH chunks (chunk = 2 k-pairs = 4 k of this lane's K-half).
// acc[e] = gate g0, acc[8+e] = gate g1 (this lane's gate-pair plane).
// wbase: seg + kp*PQ*512 + gp*256 + j*4 baked. hbase: buf + kp k-offset baked.
template<int NCH, int HS>
__device__ __forceinline__ void gemmgp(u64* __restrict__ acc,
                                       const float* __restrict__ wbase,
                                       const float* __restrict__ hbase)
{
#pragma unroll
    for (int c = 0; c < NCH; ++c) {
        ulonglong2 hv[8];
#pragma unroll
        for (int e = 0; e < 8; ++e) hv[e] = lds2(hbase + e * HS + c * 4);
#pragma unroll
        for (int ki2 = 0; ki2 < 2; ++ki2) {
            const ulonglong2 wv = lds2(wbase + (size_t)(c * 2 + ki2) * 512);
#pragma unroll
            for (int e = 0; e < 8; ++e) {
                const u64 h = ki2 ? hv[e].y : hv[e].x;
                acc[e]     = fma2(wv.x, h, acc[e]);
                acc[8 + e] = fma2(wv.y, h, acc[8 + e]);
            }
        }
    }
}

__global__ void __launch_bounds__(NT, 1)
lstm2_kernel(const float* __restrict__ x,
             const float* __restrict__ Wih0, const float* __restrict__ Whh0,
             const float* __restrict__ bih0, const float* __restrict__ bhh0,
             const float* __restrict__ Wih1, const float* __restrict__ Whh1,
             const float* __restrict__ bih1, const float* __restrict__ bhh1,
             const float* __restrict__ Wfc,  const float* __restrict__ bfc,
             float* __restrict__ out)
{
    extern __shared__ float sh[];
    const int tid = threadIdx.x;

    // ---- stage weights ----
    // W_ih0: [256 x 16], pairs 0..7, half = 4 pairs
    for (int idx = tid; idx < 256 * 16; idx += NT) {
        const int gr = idx >> 4, k = idx & 15;
        const int gate = gr >> 6, j = gr & 63;
        const int p2 = k >> 1, kp = p2 >> 2, lp = p2 & 3;
        sh[OFF_W0X + (kp * 4 + lp) * 512 + (gate >> 1) * 256 + j * 4
           + (gate & 1) * 2 + (k & 1)] = Wih0[idx];
    }
    // K=64 segments: pairs 0..31, half = 16 pairs
    for (int idx = tid; idx < 256 * 64; idx += NT) {
        const int gr = idx >> 6, k = idx & 63;
        const int gate = gr >> 6, j = gr & 63;
        const int p2 = k >> 1, kp = p2 >> 4, lp = p2 & 15;
        const int o = (kp * 16 + lp) * 512 + (gate >> 1) * 256 + j * 4
                      + (gate & 1) * 2 + (k & 1);
        sh[OFF_W0H + o] = Whh0[idx];
        sh[OFF_W1X + o] = Wih1[idx];
        sh[OFF_W1H + o] = Whh1[idx];
    }
    // combined biases: [layer][gate*64 + j]
    sh[OFF_B + tid]       = bih0[tid] + bhh0[tid];
    sh[OFF_B + 256 + tid] = bih1[tid] + bhh1[tid];
    // zero h buffers (h0 + h1, both bufs)
    for (int idx = tid; idx < 2048; idx += NT) sh[OFF_H0 + idx] = 0.0f;

    // ---- thread mapping: warp = j-octant; lane = gp*16 + kp*8 + j8 ----
    const int wid = tid >> 5, lane = tid & 31;
    const int j8  = lane & 7;
    const int kp  = (lane >> 3) & 1;     // K-half
    const int gp  = lane >> 4;           // gate-pair: 0 -> (i,f), 1 -> (g,o)
    const int j   = wid * 8 + j8;

    // x staging: kp==1, gp==0 octet; (elem = wid, k-pair = j8)
    const bool xstage = (kp == 1 && gp == 0);
    const float* xptr = x + (size_t)(blockIdx.x * 8 + wid) * T_STEPS * 16 + j8 * 2;
    float2 xv = make_float2(0.f, 0.f);
    if (xstage) {
        const float2 x0 = *reinterpret_cast<const float2*>(xptr);
        *reinterpret_cast<float2*>(&sh[OFF_X + wid * 16 + j8 * 2]) = x0;   // buf 0
        xv = *reinterpret_cast<const float2*>(xptr + 16);                  // x(1)
    }
    __syncthreads();

    // all 4 gate biases for this lane's j (act lanes use them)
    const float b0i = sh[OFF_B +   0 + j], b0f = sh[OFF_B +  64 + j];
    const float b0g = sh[OFF_B + 128 + j], b0o = sh[OFF_B + 192 + j];
    const float b1i = sh[OFF_B + 256 + j], b1f = sh[OFF_B + 320 + j];
    const float b1g = sh[OFF_B + 384 + j], b1o = sh[OFF_B + 448 + j];

    // lane-baked weight bases (gate-pair plane + K-half + j)
    const int wl = gp * 256 + j * 4;
    const float* w0x = &sh[OFF_W0X + (kp * 4)  * 512 + wl];
    const float* w0h = &sh[OFF_W0H + (kp * 16) * 512 + wl];
    const float* w1x = &sh[OFF_W1X + (kp * 16) * 512 + wl];
    const float* w1h = &sh[OFF_W1H + (kp * 16) * 512 + wl];

    const bool act = (kp == 0);          // kp==0 lanes finalize; gp selects elem quartet
    float c0[4] = {0.f, 0.f, 0.f, 0.f};  // cell state for this lane's elem quartet
    float c1[4] = {0.f, 0.f, 0.f, 0.f};

    int p = 0;
    for (int t = 0; t < T_STEPS; ++t) {
        __syncthreads();   // BAR A: x(t), h0(t-1), h1(t-1) visible

        // ================= Layer 0 =================
        u64 acc[16];
#pragma unroll
        for (int i = 0; i < 16; ++i) acc[i] = 0ull;
        gemmgp<2, 16>(acc, w0x, &sh[OFF_X + p * 128 + kp * 8]);
        gemmgp<8, 64>(acc, w0h, &sh[OFF_H0 + p * 512 + kp * 32]);

        float s0[8], s1[8];
#pragma unroll
        for (int e = 0; e < 8; ++e) { s0[e] = foldadd(acc[e]); s1[e] = foldadd(acc[8 + e]); }
#pragma unroll
        for (int e = 0; e < 8; ++e) {
            s0[e] += __shfl_xor_sync(0xffffffffu, s0[e], 8);
            s1[e] += __shfl_xor_sync(0xffffffffu, s1[e], 8);
        }
        {
            float* hw = &sh[OFF_H0 + (1 - p) * 512 + j];
#pragma unroll
            for (int q = 0; q < 4; ++q) {
                const float send0 = gp ? s0[q] : s0[4 + q];
                const float send1 = gp ? s1[q] : s1[4 + q];
                const float r0 = __shfl_xor_sync(0xffffffffu, send0, 16);
                const float r1 = __shfl_xor_sync(0xffffffffu, send1, 16);
                if (act) {
                    const float own0 = gp ? s0[4 + q] : s0[q];
                    const float own1 = gp ? s1[4 + q] : s1[q];
                    const float gi = sigf((gp ? r0 : own0) + b0i);
                    const float gf = sigf((gp ? r1 : own1) + b0f);
                    const float gg = tanhe((gp ? own0 : r0) + b0g);
                    const float go = sigf((gp ? own1 : r1) + b0o);
                    c0[q] = fmaf(gf, c0[q], gi * gg);
                    const int em = gp ? 4 + q : q;
                    hw[em * 64] = go * tanhe(c0[q]);
                }
            }
        }
        if (xstage) {
            if (t + 1 < T_STEPS)
                *reinterpret_cast<float2*>(&sh[OFF_X + (1 - p) * 128 + wid * 16 + j8 * 2]) = xv;
            if (t + 2 < T_STEPS)
                xv = *reinterpret_cast<const float2*>(xptr + (size_t)(t + 2) * 16);
        }
        __syncthreads();   // BAR B: h0(t), x(t+1) visible

        // ================= Layer 1 =================
#pragma unroll
        for (int i = 0; i < 16; ++i) acc[i] = 0ull;
        gemmgp<8, 64>(acc, w1x, &sh[OFF_H0 + (1 - p) * 512 + kp * 32]);
        gemmgp<8, 64>(acc, w1h, &sh[OFF_H1 + p * 512 + kp * 32]);

#pragma unroll
        for (int e = 0; e < 8; ++e) { s0[e] = foldadd(acc[e]); s1[e] = foldadd(acc[8 + e]); }
#pragma unroll
        for (int e = 0; e < 8; ++e) {
            s0[e] += __shfl_xor_sync(0xffffffffu, s0[e], 8);
            s1[e] += __shfl_xor_sync(0xffffffffu, s1[e], 8);
        }
        {
            float* hw = &sh[OFF_H1 + (1 - p) * 512 + j];
#pragma unroll
            for (int q = 0; q < 4; ++q) {
                const float send0 = gp ? s0[q] : s0[4 + q];
                const float send1 = gp ? s1[q] : s1[4 + q];
                const float r0 = __shfl_xor_sync(0xffffffffu, send0, 16);
                const float r1 = __shfl_xor_sync(0xffffffffu, send1, 16);
                if (act) {
                    const float own0 = gp ? s0[4 + q] : s0[q];
                    const float own1 = gp ? s1[4 + q] : s1[q];
                    const float gi = sigf((gp ? r0 : own0) + b1i);
                    const float gf = sigf((gp ? r1 : own1) + b1f);
                    const float gg = tanhe((gp ? own0 : r0) + b1g);
                    const float go = sigf((gp ? own1 : r1) + b1o);
                    c1[q] = fmaf(gf, c1[q], gi * gg);
                    const int em = gp ? 4 + q : q;
                    hw[em * 64] = go * tanhe(c1[q]);
                }
            }
        }
        p ^= 1;
    }

    __syncthreads();

    // ---- FC head: out[b] = dot(Wfc, h1_last[b]) + bfc ----
    if (tid < 8) {
        const float* hv = &sh[OFF_H1 + p * 512 + tid * 64];
        float sum = 0.0f;
#pragma unroll 8
        for (int k = 0; k < 64; ++k) sum += Wfc[k] * hv[k];
        out[blockIdx.x * 8 + tid] = sum + bfc[0];
    }
}

extern "C" void kernel_launch(void* const* d_in, const int* in_sizes, int n_in,
                              void* d_out, int out_size)
{
    const float* x    = (const float*)d_in[0];
    const float* Wih0 = (const float*)d_in[1];
    const float* Whh0 = (const float*)d_in[2];
    const float* bih0 = (const float*)d_in[3];
    const float* bhh0 = (const float*)d_in[4];
    const float* Wih1 = (const float*)d_in[5];
    const float* Whh1 = (const float*)d_in[6];
    const float* bih1 = (const float*)d_in[7];
    const float* bhh1 = (const float*)d_in[8];
    const float* Wfc  = (const float*)d_in[9];
    const float* bfc  = (const float*)d_in[10];
    float* out = (float*)d_out;

    cudaFuncSetAttribute(lstm2_kernel,
                         cudaFuncAttributeMaxDynamicSharedMemorySize, SMEM_BYTES);
    lstm2_kernel<<<NCTAS, NT, SMEM_BYTES>>>(
        x, Wih0, Whh0, bih0, bhh0, Wih1, Whh1, bih1, bhh1, Wfc, bfc, out);
}

// round 12
// speedup vs baseline: 1.5680x; 1.5680x over previous
#include <cuda_runtime.h>
#include <cstddef>

// Fixed shapes
#define T_STEPS 336
#define NT      256          // 8 warps, 2 per SMSP
#define NCTAS   128          // 8 batch elems per CTA

typedef unsigned long long u64;

// ---- shared memory layout (float offsets) ---- (identical to the 1243us kernel)
// Weights: per k-pair row (stride WS=520 floats):
//   floats [0..255]  : plane01 -> j*4 + {Wi_k, Wi_k1, Wf_k, Wf_k1}
//   floats [256..511]: plane23 -> j*4 + {Wg_k, Wg_k1, Wo_k, Wo_k1}
// Rows within a segment interleaved by split-K half: row = local_pair*2 + kpar.
#define WS      520
#define OFF_W0X 0            // K=16  -> 8 rows
#define OFF_W0H 4160         // K=64  -> 32 rows
#define OFF_W1X 20800        // K=64  -> 32 rows
#define OFF_W1H 37440        // K=64  -> 32 rows
#define OFF_B   54080        // 512: combined biases, [layer*256 + gate*64 + j]
#define OFF_X   54592        // 2 bufs x (8 elems x 20)
#define OFF_H0  54912        // 2 bufs x (8 elems x 68), k-swizzled pos(k)=k+(k>=32)*4
#define OFF_H1  56000        // 2 bufs x 544
#define SMEM_FLOATS 57088
#define SMEM_BYTES (SMEM_FLOATS * 4)   // 228,352 B < 232,448 cap

// ---- packed helpers ----
__device__ __forceinline__ u64 fma2(u64 a, u64 b, u64 c) {
    u64 d;
    asm("fma.rn.f32x2 %0, %1, %2, %3;" : "=l"(d) : "l"(a), "l"(b), "l"(c));
    return d;
}
__device__ __forceinline__ ulonglong2 lds2(const float* p) {
    return *reinterpret_cast<const ulonglong2*>(p);
}
__device__ __forceinline__ float foldadd(u64 v) {
    float lo, hi;
    asm("mov.b64 {%0,%1}, %2;" : "=f"(lo), "=f"(hi) : "l"(v));
    return lo + hi;
}
__device__ __forceinline__ float sigf(float x) {
    return __fdividef(1.0f, 1.0f + __expf(-x));
}
__device__ __forceinline__ float tanhe(float x) {
    return 1.0f - __fdividef(2.0f, __expf(2.0f * x) + 1.0f);
}

// GEMM over NCH chunks of 4 k (= 2 k-pairs). acc[gate*4+e], gates i,f,g,o.
// wbase: segment base + kpar*WS + j*4 baked in. hbase: buf + e0*HS + kpar-k-offset baked in.
template<int NCH, int HS>
__device__ __forceinline__ void gemm2(u64* __restrict__ acc,
                                      const float* __restrict__ wbase,
                                      const float* __restrict__ hbase)
{
#pragma unroll
    for (int c = 0; c < NCH; ++c) {
        ulonglong2 hv0 = lds2(hbase + 0 * HS + c * 4);
        ulonglong2 hv1 = lds2(hbase + 1 * HS + c * 4);
        ulonglong2 hv2 = lds2(hbase + 2 * HS + c * 4);
        ulonglong2 hv3 = lds2(hbase + 3 * HS + c * 4);
#pragma unroll
        for (int ki2 = 0; ki2 < 2; ++ki2) {
            const float* wr = wbase + (size_t)(4 * c + 2 * ki2) * WS;
            const ulonglong2 wif = lds2(wr);
            const ulonglong2 wgo = lds2(wr + 256);
            const u64 h0 = ki2 ? hv0.y : hv0.x;
            const u64 h1 = ki2 ? hv1.y : hv1.x;
            const u64 h2 = ki2 ? hv2.y : hv2.x;
            const u64 h3 = ki2 ? hv3.y : hv3.x;
            acc[0]  = fma2(wif.x, h0, acc[0]);
            acc[1]  = fma2(wif.x, h1, acc[1]);
            acc[2]  = fma2(wif.x, h2, acc[2]);
            acc[3]  = fma2(wif.x, h3, acc[3]);
            acc[4]  = fma2(wif.y, h0, acc[4]);
            acc[5]  = fma2(wif.y, h1, acc[5]);
            acc[6]  = fma2(wif.y, h2, acc[6]);
            acc[7]  = fma2(wif.y, h3, acc[7]);
            acc[8]  = fma2(wgo.x, h0, acc[8]);
            acc[9]  = fma2(wgo.x, h1, acc[9]);
            acc[10] = fma2(wgo.x, h2, acc[10]);
            acc[11] = fma2(wgo.x, h3, acc[11]);
            acc[12] = fma2(wgo.y, h0, acc[12]);
            acc[13] = fma2(wgo.y, h1, acc[13]);
            acc[14] = fma2(wgo.y, h2, acc[14]);
            acc[15] = fma2(wgo.y, h3, acc[15]);
        }
    }
}

__device__ __forceinline__ void combine16(u64* __restrict__ acc, float* __restrict__ s) {
#pragma unroll
    for (int i = 0; i < 16; ++i) s[i] = foldadd(acc[i]);
#pragma unroll
    for (int i = 0; i < 16; ++i) s[i] += __shfl_xor_sync(0xffffffffu, s[i], 16);
}

// kp==0 lanes only: activations for 4 elems; hw points at elem e0, swizzled j baked in.
__device__ __forceinline__ void act4(const float* __restrict__ s,
                                     float bi, float bf, float bg, float bo,
                                     float* __restrict__ c, float* __restrict__ hw)
{
#pragma unroll
    for (int e = 0; e < 4; ++e) {
        const float gi = sigf(s[e] + bi);
        const float gf = sigf(s[4 + e] + bf);
        const float gg = tanhe(s[8 + e] + bg);
        const float go = sigf(s[12 + e] + bo);
        c[e] = fmaf(gf, c[e], gi * gg);
        hw[e * 68] = go * tanhe(c[e]);
    }
}

__global__ void __launch_bounds__(NT, 1)
lstm2_kernel(const float* __restrict__ x,
             const float* __restrict__ Wih0, const float* __restrict__ Whh0,
             const float* __restrict__ bih0, const float* __restrict__ bhh0,
             const float* __restrict__ Wih1, const float* __restrict__ Whh1,
             const float* __restrict__ bih1, const float* __restrict__ bhh1,
             const float* __restrict__ Wfc,  const float* __restrict__ bfc,
             float* __restrict__ out)
{
    extern __shared__ float sh[];
    const int tid = threadIdx.x;

    // ---- stage weights into k-pair-packed layout (identical to 1243us kernel) ----
    for (int idx = tid; idx < 256 * 16; idx += NT) {
        const int gr = idx >> 4, k = idx & 15;
        const int g = gr >> 6, j = gr & 63;
        const int p2 = k >> 1;
        const int kh = (p2 >= 4) ? 1 : 0;
        const int row = (p2 - kh * 4) * 2 + kh;
        sh[OFF_W0X + row * WS + (g >> 1) * 256 + j * 4 + (g & 1) * 2 + (k & 1)] = Wih0[idx];
    }
    for (int idx = tid; idx < 256 * 64; idx += NT) {
        const int gr = idx >> 6, k = idx & 63;
        const int g = gr >> 6, j = gr & 63;
        const int p2 = k >> 1;
        const int kh = (p2 >= 16) ? 1 : 0;
        const int row = (p2 - kh * 16) * 2 + kh;
        const int o = row * WS + (g >> 1) * 256 + j * 4 + (g & 1) * 2 + (k & 1);
        sh[OFF_W0H + o] = Whh0[idx];
        sh[OFF_W1X + o] = Wih1[idx];
        sh[OFF_W1H + o] = Whh1[idx];
    }
    if (tid < 256) {
        sh[OFF_B + tid]       = bih0[tid] + bhh0[tid];
        sh[OFF_B + 256 + tid] = bih1[tid] + bhh1[tid];
    }
    // zero h buffers (h0+h1, both bufs: 2176 floats)
    for (int idx = tid; idx < 2176; idx += NT) sh[OFF_H0 + idx] = 0.0f;

    // ---- thread mapping (identical): warp=(eg,jq); lane=(kp,hl) ----
    const int wid = tid >> 5, lane = tid & 31;
    const int eg  = wid >> 2;
    const int jq  = wid & 3;
    const int hl  = lane & 15;
    const int kp  = lane >> 4;
    const int j   = jq * 16 + hl;
    const int e0  = eg * 4;

    // x staging owned by kp==1 lanes: pid 0..127 -> (elem, k)
    const int pid = wid * 16 + hl;
    const int xe = pid >> 4, xk = pid & 15;
    const float* xptr = x + ((size_t)(blockIdx.x * 8 + xe) * T_STEPS) * 16 + xk;
    float xreg = 0.0f;
    if (kp == 1) {
        sh[OFF_X + xe * 20 + xk] = xptr[0];   // x(0) -> buf 0
        xreg = xptr[16];                      // prefetch x(1)
    }
    __syncthreads();

    const float b0i = sh[OFF_B +   0 + j], b0f = sh[OFF_B +  64 + j];
    const float b0g = sh[OFF_B + 128 + j], b0o = sh[OFF_B + 192 + j];
    const float b1i = sh[OFF_B + 256 + j], b1f = sh[OFF_B + 320 + j];
    const float b1g = sh[OFF_B + 384 + j], b1o = sh[OFF_B + 448 + j];

    const float* w0x = &sh[OFF_W0X + kp * WS + j * 4];
    const float* w0h = &sh[OFF_W0H + kp * WS + j * 4];
    const float* w1x = &sh[OFF_W1X + kp * WS + j * 4];
    const float* w1h = &sh[OFF_W1H + kp * WS + j * 4];
    const int hko = kp * 36;             // swizzled k-offset for this K-half
    const int pj  = j + ((j >> 5) << 2); // swizzled j for h stores
    float c0[4] = {0.f, 0.f, 0.f, 0.f};
    float c1[4] = {0.f, 0.f, 0.f, 0.f};
    float s[16];

    // ================= Prologue: L0(0) =================
    {
        u64 acc[16];
#pragma unroll
        for (int i = 0; i < 16; ++i) acc[i] = 0ull;
        gemm2<2, 20>(acc, w0x, &sh[OFF_X + 0 * 160 + e0 * 20 + kp * 8]);    // x(0) buf0
        gemm2<8, 68>(acc, w0h, &sh[OFF_H0 + 1 * 544 + e0 * 68 + hko]);      // zeros buf1
        combine16(acc, s);
        if (kp == 0) {
            act4(s, b0i, b0f, b0g, b0o, c0, &sh[OFF_H0 + 0 * 544 + e0 * 68 + pj]); // h0(0)->buf0
        } else {
            sh[OFF_X + 1 * 160 + xe * 20 + xk] = xreg;       // x(1) -> buf1
            xreg = xptr[2 * 16];                             // prefetch x(2)
        }
    }

    // ================= Main windows w = 0..334: L1(w) + L0(w+1) =================
    int p = 0;   // p = w & 1
    for (int w = 0; w < T_STEPS - 1; ++w) {
        __syncthreads();   // h0(w)@p, h1(w-1)@1-p, x(w+1)@1-p all visible

        u64 accA[16], accB[16];
#pragma unroll
        for (int i = 0; i < 16; ++i) { accA[i] = 0ull; accB[i] = 0ull; }

        // L1(w): reads h0(w)@p, h1(w-1)@1-p
        gemm2<8, 68>(accA, w1x, &sh[OFF_H0 + p * 544 + e0 * 68 + hko]);
        gemm2<8, 68>(accA, w1h, &sh[OFF_H1 + (1 - p) * 544 + e0 * 68 + hko]);
        // L0(w+1): reads x(w+1)@1-p, h0(w)@p
        gemm2<2, 20>(accB, w0x, &sh[OFF_X + (1 - p) * 160 + e0 * 20 + kp * 8]);
        gemm2<8, 68>(accB, w0h, &sh[OFF_H0 + p * 544 + e0 * 68 + hko]);

        combine16(accA, s);
        if (kp == 0) {
            act4(s, b1i, b1f, b1g, b1o, c1, &sh[OFF_H1 + p * 544 + e0 * 68 + pj]); // h1(w)->@p
        } else {
            if (w + 2 < T_STEPS)
                sh[OFF_X + p * 160 + xe * 20 + xk] = xreg;   // x(w+2) -> @p
            if (w + 3 < T_STEPS)
                xreg = xptr[(size_t)(w + 3) * 16];
        }
        combine16(accB, s);
        if (kp == 0) {
            act4(s, b0i, b0f, b0g, b0o, c0,
                 &sh[OFF_H0 + (1 - p) * 544 + e0 * 68 + pj]);                // h0(w+1)->@1-p
        }
        p ^= 1;
    }

    // ================= Epilogue: L1(335) =================  (p == 1 here)
    __syncthreads();
    {
        u64 acc[16];
#pragma unroll
        for (int i = 0; i < 16; ++i) acc[i] = 0ull;
        gemm2<8, 68>(acc, w1x, &sh[OFF_H0 + 1 * 544 + e0 * 68 + hko]);   // h0(335)@1
        gemm2<8, 68>(acc, w1h, &sh[OFF_H1 + 0 * 544 + e0 * 68 + hko]);   // h1(334)@0
        combine16(acc, s);
        if (kp == 0) {
            act4(s, b1i, b1f, b1g, b1o, c1, &sh[OFF_H1 + 1 * 544 + e0 * 68 + pj]); // h1(335)->@1
        }
    }
    __syncthreads();

    // ---- FC head: out[b] = dot(Wfc, h1_last[b]) + bfc ---- (h1(335) in buf 1)
    if (tid < 8) {
        const float* hv = &sh[OFF_H1 + 1 * 544 + tid * 68];
        float sum = 0.0f;
#pragma unroll 8
        for (int k = 0; k < 64; ++k) sum += Wfc[k] * hv[k + ((k >> 5) << 2)];
        out[blockIdx.x * 8 + tid] = sum + bfc[0];
    }
}

extern "C" void kernel_launch(void* const* d_in, const int* in_sizes, int n_in,
                              void* d_out, int out_size)
{
    const float* x    = (const float*)d_in[0];
    const float* Wih0 = (const float*)d_in[1];
    const float* Whh0 = (const float*)d_in[2];
    const float* bih0 = (const float*)d_in[3];
    const float* bhh0 = (const float*)d_in[4];
    const float* Wih1 = (const float*)d_in[5];
    const float* Whh1 = (const float*)d_in[6];
    const float* bih1 = (const float*)d_in[7];
    const float* bhh1 = (const float*)d_in[8];
    const float* Wfc  = (const float*)d_in[9];
    const float* bfc  = (const float*)d_in[10];
    float* out = (float*)d_out;

    cudaFuncSetAttribute(lstm2_kernel,
                         cudaFuncAttributeMaxDynamicSharedMemorySize, SMEM_BYTES);
    lstm2_kernel<<<NCTAS, NT, SMEM_BYTES>>>(
        x, Wih0, Whh0, bih0, bhh0, Wih1, Whh1, bih1, bhh1, Wfc, bfc, out);
}

// round 13
// speedup vs baseline: 1.8422x; 1.1748x over previous
#include <cuda_runtime.h>
#include <cstddef>

// Fixed shapes
#define T_STEPS 336
#define NT      256          // 8 warps, 2 per SMSP
#define NCTAS   128          // 8 batch elems per CTA

typedef unsigned long long u64;

// ---- shared memory layout (float offsets) ---- (identical to the 1243/1194us kernels)
#define WS      520
#define OFF_W0X 0            // K=16  -> 8 rows
#define OFF_W0H 4160         // K=64  -> 32 rows
#define OFF_W1X 20800        // K=64  -> 32 rows
#define OFF_W1H 37440        // K=64  -> 32 rows
#define OFF_B   54080        // 512: combined biases, [layer*256 + gate*64 + j]
#define OFF_X   54592        // 2 bufs x (8 elems x 20)
#define OFF_H0  54912        // 2 bufs x (8 elems x 68), k-swizzled pos(k)=k+(k>=32)*4
#define OFF_H1  56000        // 2 bufs x 544
#define SMEM_FLOATS 57088
#define SMEM_BYTES (SMEM_FLOATS * 4)   // 228,352 B < 232,448 cap

// group-local barrier: 128 threads of one eg-group
#define BARG(id) asm volatile("bar.sync %0, %1;" :: "r"(id), "r"(128) : "memory")

// ---- packed helpers ----
__device__ __forceinline__ u64 fma2(u64 a, u64 b, u64 c) {
    u64 d;
    asm("fma.rn.f32x2 %0, %1, %2, %3;" : "=l"(d) : "l"(a), "l"(b), "l"(c));
    return d;
}
__device__ __forceinline__ ulonglong2 lds2(const float* p) {
    return *reinterpret_cast<const ulonglong2*>(p);
}
__device__ __forceinline__ float foldadd(u64 v) {
    float lo, hi;
    asm("mov.b64 {%0,%1}, %2;" : "=f"(lo), "=f"(hi) : "l"(v));
    return lo + hi;
}
__device__ __forceinline__ float sigf(float x) {
    return __fdividef(1.0f, 1.0f + __expf(-x));
}
__device__ __forceinline__ float tanhe(float x) {
    return 1.0f - __fdividef(2.0f, __expf(2.0f * x) + 1.0f);
}

// GEMM over NCH chunks of 4 k (= 2 k-pairs). acc[gate*4+e], gates i,f,g,o.
template<int NCH, int HS>
__device__ __forceinline__ void gemm2(u64* __restrict__ acc,
                                      const float* __restrict__ wbase,
                                      const float* __restrict__ hbase)
{
#pragma unroll
    for (int c = 0; c < NCH; ++c) {
        ulonglong2 hv0 = lds2(hbase + 0 * HS + c * 4);
        ulonglong2 hv1 = lds2(hbase + 1 * HS + c * 4);
        ulonglong2 hv2 = lds2(hbase + 2 * HS + c * 4);
        ulonglong2 hv3 = lds2(hbase + 3 * HS + c * 4);
#pragma unroll
        for (int ki2 = 0; ki2 < 2; ++ki2) {
            const float* wr = wbase + (size_t)(4 * c + 2 * ki2) * WS;
            const ulonglong2 wif = lds2(wr);
            const ulonglong2 wgo = lds2(wr + 256);
            const u64 h0 = ki2 ? hv0.y : hv0.x;
            const u64 h1 = ki2 ? hv1.y : hv1.x;
            const u64 h2 = ki2 ? hv2.y : hv2.x;
            const u64 h3 = ki2 ? hv3.y : hv3.x;
            acc[0]  = fma2(wif.x, h0, acc[0]);
            acc[1]  = fma2(wif.x, h1, acc[1]);
            acc[2]  = fma2(wif.x, h2, acc[2]);
            acc[3]  = fma2(wif.x, h3, acc[3]);
            acc[4]  = fma2(wif.y, h0, acc[4]);
            acc[5]  = fma2(wif.y, h1, acc[5]);
            acc[6]  = fma2(wif.y, h2, acc[6]);
            acc[7]  = fma2(wif.y, h3, acc[7]);
            acc[8]  = fma2(wgo.x, h0, acc[8]);
            acc[9]  = fma2(wgo.x, h1, acc[9]);
            acc[10] = fma2(wgo.x, h2, acc[10]);
            acc[11] = fma2(wgo.x, h3, acc[11]);
            acc[12] = fma2(wgo.y, h0, acc[12]);
            acc[13] = fma2(wgo.y, h1, acc[13]);
            acc[14] = fma2(wgo.y, h2, acc[14]);
            acc[15] = fma2(wgo.y, h3, acc[15]);
        }
    }
}

__device__ __forceinline__ void combine16(u64* __restrict__ acc, float* __restrict__ s) {
#pragma unroll
    for (int i = 0; i < 16; ++i) s[i] = foldadd(acc[i]);
#pragma unroll
    for (int i = 0; i < 16; ++i) s[i] += __shfl_xor_sync(0xffffffffu, s[i], 16);
}

// Split activation: kp0 lanes finalize elems {0,1}, kp1 lanes elems {2,3} of the quartet.
// All indices into s are compile-time (selects, not dynamic indexing).
__device__ __forceinline__ void act2sel(const float* __restrict__ s, int kp,
                                        float bi, float bf, float bg, float bo,
                                        float* __restrict__ c, float* __restrict__ hw)
{
#pragma unroll
    for (int q = 0; q < 2; ++q) {
        const float si = kp ? s[2 + q]  : s[q];
        const float sf = kp ? s[6 + q]  : s[4 + q];
        const float sg = kp ? s[10 + q] : s[8 + q];
        const float so = kp ? s[14 + q] : s[12 + q];
        const float gi = sigf(si + bi);
        const float gf = sigf(sf + bf);
        const float gg = tanhe(sg + bg);
        const float go = sigf(so + bo);
        c[q] = fmaf(gf, c[q], gi * gg);
        hw[(2 * kp + q) * 68] = go * tanhe(c[q]);
    }
}

__global__ void __launch_bounds__(NT, 1)
lstm2_kernel(const float* __restrict__ x,
             const float* __restrict__ Wih0, const float* __restrict__ Whh0,
             const float* __restrict__ bih0, const float* __restrict__ bhh0,
             const float* __restrict__ Wih1, const float* __restrict__ Whh1,
             const float* __restrict__ bih1, const float* __restrict__ bhh1,
             const float* __restrict__ Wfc,  const float* __restrict__ bfc,
             float* __restrict__ out)
{
    extern __shared__ float sh[];
    const int tid = threadIdx.x;

    // ---- stage weights into k-pair-packed layout ----
    for (int idx = tid; idx < 256 * 16; idx += NT) {
        const int gr = idx >> 4, k = idx & 15;
        const int g = gr >> 6, j = gr & 63;
        const int p2 = k >> 1;
        const int kh = (p2 >= 4) ? 1 : 0;
        const int row = (p2 - kh * 4) * 2 + kh;
        sh[OFF_W0X + row * WS + (g >> 1) * 256 + j * 4 + (g & 1) * 2 + (k & 1)] = Wih0[idx];
    }
    for (int idx = tid; idx < 256 * 64; idx += NT) {
        const int gr = idx >> 6, k = idx & 63;
        const int g = gr >> 6, j = gr & 63;
        const int p2 = k >> 1;
        const int kh = (p2 >= 16) ? 1 : 0;
        const int row = (p2 - kh * 16) * 2 + kh;
        const int o = row * WS + (g >> 1) * 256 + j * 4 + (g & 1) * 2 + (k & 1);
        sh[OFF_W0H + o] = Whh0[idx];
        sh[OFF_W1X + o] = Wih1[idx];
        sh[OFF_W1H + o] = Whh1[idx];
    }
    if (tid < 256) {
        sh[OFF_B + tid]       = bih0[tid] + bhh0[tid];
        sh[OFF_B + 256 + tid] = bih1[tid] + bhh1[tid];
    }
    for (int idx = tid; idx < 2176; idx += NT) sh[OFF_H0 + idx] = 0.0f;

    // ---- thread mapping: warp=(eg,jq); lane=(kp,hl) ----
    const int wid = tid >> 5, lane = tid & 31;
    const int eg  = wid >> 2;
    const int jq  = wid & 3;
    const int hl  = lane & 15;
    const int kp  = lane >> 4;
    const int j   = jq * 16 + hl;
    const int e0  = eg * 4;
    const int gid = eg + 1;              // named barrier id for this group

    // x staging owned by kp==1 lanes: pid 0..127 -> (elem, k)
    const int pid = wid * 16 + hl;
    const int xe = pid >> 4, xk = pid & 15;
    const float* xptr = x + ((size_t)(blockIdx.x * 8 + xe) * T_STEPS) * 16 + xk;
    float xreg = 0.0f;
    if (kp == 1) {
        sh[OFF_X + xe * 20 + xk] = xptr[0];   // x(0) -> buf 0
        xreg = xptr[16];                      // prefetch x(1)
    }
    __syncthreads();

    const float b0i = sh[OFF_B +   0 + j], b0f = sh[OFF_B +  64 + j];
    const float b0g = sh[OFF_B + 128 + j], b0o = sh[OFF_B + 192 + j];
    const float b1i = sh[OFF_B + 256 + j], b1f = sh[OFF_B + 320 + j];
    const float b1g = sh[OFF_B + 384 + j], b1o = sh[OFF_B + 448 + j];

    const float* w0x = &sh[OFF_W0X + kp * WS + j * 4];
    const float* w0h = &sh[OFF_W0H + kp * WS + j * 4];
    const float* w1x = &sh[OFF_W1X + kp * WS + j * 4];
    const float* w1h = &sh[OFF_W1H + kp * WS + j * 4];
    const int hko = kp * 36;             // swizzled k-offset for this K-half
    const int pj  = j + ((j >> 5) << 2); // swizzled j for h stores
    float c0[2] = {0.f, 0.f};            // cell state for this lane's 2 elems
    float c1[2] = {0.f, 0.f};
    float s[16];

    // ================= Prologue: L0(0) =================
    {
        u64 acc[16];
#pragma unroll
        for (int i = 0; i < 16; ++i) acc[i] = 0ull;
        gemm2<2, 20>(acc, w0x, &sh[OFF_X + 0 * 160 + e0 * 20 + kp * 8]);    // x(0) buf0
        gemm2<8, 68>(acc, w0h, &sh[OFF_H0 + 1 * 544 + e0 * 68 + hko]);      // zeros buf1
        combine16(acc, s);
        act2sel(s, kp, b0i, b0f, b0g, b0o, c0,
                &sh[OFF_H0 + 0 * 544 + e0 * 68 + pj]);                      // h0(0)->buf0
        if (kp == 1) {
            sh[OFF_X + 1 * 160 + xe * 20 + xk] = xreg;       // x(1) -> buf1
            xreg = xptr[2 * 16];                             // prefetch x(2)
        }
    }

    // ================= Main windows w = 0..334: L1(w) + L0(w+1) =================
    int p = 0;   // p = w & 1
    for (int w = 0; w < T_STEPS - 1; ++w) {
        BARG(gid);   // group-local: h0(w)@p, h1(w-1)@1-p, x(w+1)@1-p visible

        u64 accA[16], accB[16];
#pragma unroll
        for (int i = 0; i < 16; ++i) { accA[i] = 0ull; accB[i] = 0ull; }

        // L1(w): reads h0(w)@p, h1(w-1)@1-p
        gemm2<8, 68>(accA, w1x, &sh[OFF_H0 + p * 544 + e0 * 68 + hko]);
        gemm2<8, 68>(accA, w1h, &sh[OFF_H1 + (1 - p) * 544 + e0 * 68 + hko]);
        // L0(w+1): reads x(w+1)@1-p, h0(w)@p
        gemm2<2, 20>(accB, w0x, &sh[OFF_X + (1 - p) * 160 + e0 * 20 + kp * 8]);
        gemm2<8, 68>(accB, w0h, &sh[OFF_H0 + p * 544 + e0 * 68 + hko]);

        combine16(accA, s);
        act2sel(s, kp, b1i, b1f, b1g, b1o, c1,
                &sh[OFF_H1 + p * 544 + e0 * 68 + pj]);                     // h1(w)->@p
        if (kp == 1) {
            if (w + 2 < T_STEPS)
                sh[OFF_X + p * 160 + xe * 20 + xk] = xreg;   // x(w+2) -> @p
            if (w + 3 < T_STEPS)
                xreg = xptr[(size_t)(w + 3) * 16];
        }
        combine16(accB, s);
        act2sel(s, kp, b0i, b0f, b0g, b0o, c0,
                &sh[OFF_H0 + (1 - p) * 544 + e0 * 68 + pj]);               // h0(w+1)->@1-p
        p ^= 1;
    }

    // ================= Epilogue: L1(335) =================  (p == 1 here)
    BARG(gid);
    {
        u64 acc[16];
#pragma unroll
        for (int i = 0; i < 16; ++i) acc[i] = 0ull;
        gemm2<8, 68>(acc, w1x, &sh[OFF_H0 + 1 * 544 + e0 * 68 + hko]);   // h0(335)@1
        gemm2<8, 68>(acc, w1h, &sh[OFF_H1 + 0 * 544 + e0 * 68 + hko]);   // h1(334)@0
        combine16(acc, s);
        act2sel(s, kp, b1i, b1f, b1g, b1o, c1,
                &sh[OFF_H1 + 1 * 544 + e0 * 68 + pj]);                   // h1(335)->@1
    }
    __syncthreads();   // join both groups before FC head

    // ---- FC head: out[b] = dot(Wfc, h1_last[b]) + bfc ---- (h1(335) in buf 1)
    if (tid < 8) {
        const float* hv = &sh[OFF_H1 + 1 * 544 + tid * 68];
        float sum = 0.0f;
#pragma unroll 8
        for (int k = 0; k < 64; ++k) sum += Wfc[k] * hv[k + ((k >> 5) << 2)];
        out[blockIdx.x * 8 + tid] = sum + bfc[0];
    }
}

extern "C" void kernel_launch(void* const* d_in, const int* in_sizes, int n_in,
                              void* d_out, int out_size)
{
    const float* x    = (const float*)d_in[0];
    const float* Wih0 = (const float*)d_in[1];
    const float* Whh0 = (const float*)d_in[2];
    const float* bih0 = (const float*)d_in[3];
    const float* bhh0 = (const float*)d_in[4];
    const float* Wih1 = (const float*)d_in[5];
    const float* Whh1 = (const float*)d_in[6];
    const float* bih1 = (const float*)d_in[7];
    const float* bhh1 = (const float*)d_in[8];
    const float* Wfc  = (const float*)d_in[9];
    const float* bfc  = (const float*)d_in[10];
    float* out = (float*)d_out;

    cudaFuncSetAttribute(lstm2_kernel,
                         cudaFuncAttributeMaxDynamicSharedMemorySize, SMEM_BYTES);
    lstm2_kernel<<<NCTAS, NT, SMEM_BYTES>>>(
        x, Wih0, Whh0, bih0, bhh0, Wih1, Whh1, bih1, bhh1, Wfc, bfc, out);
}